// round 1
// baseline (speedup 1.0000x reference)
#include <cuda_runtime.h>
#include <cuda_bf16.h>

// AgentPolicy fused kernel.
// B=4096, N=64, FIN=256, D1=512, D2=128. One CTA per batch element.
// Pipeline per CTA:
//   A = [others[b] (64 rows); obs_x[b] (row 64)]  -> smem fp32
//   Z = A @ W1 + b1 (y rows 0..63, x row 64)       -> smem bf16, fp32 accum
//   alpha = x . y / sqrt(512); beta = softmax(alpha)
//   c = sum_n beta[n] * y[n]; out = [x, c] (1024)
//   o2 = softmax(out @ W2 + b2); logits = o2 + NEG*(1-mask)
// Value head (W3/b3/W4/b4) is dead in the reference -> skipped.

#define BB   4096
#define NN   64
#define FINN 256
#define DD1  512
#define DD2  128

#define A_STRIDE 264   // 256 + 8 pad (fp32)
#define Z_STRIDE 520   // 512 + 8 pad (bf16)
#define NEGC (-10000000.0f)

__global__ __launch_bounds__(512, 1)
void agent_policy_kernel(const float* __restrict__ obs_x,
                         const float* __restrict__ others,
                         const int*   __restrict__ action_mask,
                         const float* __restrict__ W1,
                         const float* __restrict__ b1,
                         const float* __restrict__ W2,
                         const float* __restrict__ b2,
                         float*       __restrict__ out)
{
    extern __shared__ char smem_raw[];
    float*          As  = (float*)smem_raw;                 // [65][264] fp32
    float*          Ws  = As + 65 * A_STRIDE;               // [32][512] fp32 (W1 k-tile)
    __nv_bfloat16*  Zs  = (__nv_bfloat16*)(Ws + 32 * 512);  // [65][520] bf16
    float*          red = (float*)(Zs + 65 * Z_STRIDE);     // [512]
    float*          bet = red + 512;                        // [64]
    float*          o2  = bet + 64;                         // [128]
    float*          msc = o2 + 128;                         // [8]

    const int t = threadIdx.x;
    const int b = blockIdx.x;

    // ---- load A: others[b] rows 0..63, obs_x[b] row 64 ----
    {
        const float* oth = others + (size_t)b * (NN * FINN);
        #pragma unroll
        for (int i = 0; i < 32; i++) {
            int idx = i * 512 + t;
            int n = idx >> 8;        // /256
            int f = idx & 255;
            As[n * A_STRIDE + f] = oth[idx];
        }
        if (t < FINN) As[64 * A_STRIDE + t] = obs_x[(size_t)b * FINN + t];
    }

    // ---- GEMM: Z[65][512] = A[65][256] @ W1[256][512] ----
    const int rg   = t >> 6;       // row group 0..7 (rows rg*8 .. rg*8+7)
    const int cg   = t & 63;       // col base; this thread owns cols cg + 64*j
    const int row0 = rg * 8;

    float acc[8][8];
    #pragma unroll
    for (int r = 0; r < 8; r++)
        #pragma unroll
        for (int j = 0; j < 8; j++)
            acc[r][j] = 0.0f;
    float xacc = 0.0f;

    for (int kt = 0; kt < 8; kt++) {
        __syncthreads();
        const float* w1p = W1 + (size_t)(kt * 32) * DD1;
        #pragma unroll
        for (int i = 0; i < 32; i++)
            Ws[i * 512 + t] = w1p[i * 512 + t];
        __syncthreads();

        const int kbase = kt * 32;
        #pragma unroll 4
        for (int k = 0; k < 32; k++) {
            const int kk = kbase + k;
            float aa[8], ww[8];
            #pragma unroll
            for (int r = 0; r < 8; r++) aa[r] = As[(row0 + r) * A_STRIDE + kk];
            #pragma unroll
            for (int j = 0; j < 8; j++) ww[j] = Ws[k * 512 + cg + 64 * j];
            #pragma unroll
            for (int r = 0; r < 8; r++)
                #pragma unroll
                for (int j = 0; j < 8; j++)
                    acc[r][j] = fmaf(aa[r], ww[j], acc[r][j]);
            // x row (row 64): thread t accumulates column t
            xacc = fmaf(As[64 * A_STRIDE + kk], Ws[k * 512 + t], xacc);
        }
    }

    // ---- epilogue: add b1, store Z as bf16 ----
    #pragma unroll
    for (int j = 0; j < 8; j++) {
        const int col = cg + 64 * j;
        const float bv = b1[col];
        #pragma unroll
        for (int r = 0; r < 8; r++)
            Zs[(row0 + r) * Z_STRIDE + col] = __float2bfloat16(acc[r][j] + bv);
    }
    Zs[64 * Z_STRIDE + t] = __float2bfloat16(xacc + b1[t]);
    __syncthreads();

    // ---- alpha[n] = x . y[n] / sqrt(512) ----
    {
        const int n = t >> 3;      // 0..63
        const int p = t & 7;       // 0..7, 64 d's each
        const __nv_bfloat16* yr = Zs + n * Z_STRIDE;
        const __nv_bfloat16* xr = Zs + 64 * Z_STRIDE;
        float s = 0.0f;
        #pragma unroll 8
        for (int d = 0; d < 64; d++) {
            int dd = p * 64 + d;
            s = fmaf(__bfloat162float(xr[dd]), __bfloat162float(yr[dd]), s);
        }
        red[t] = s;
    }
    __syncthreads();
    if (t < 64) {
        float s = 0.0f;
        #pragma unroll
        for (int p = 0; p < 8; p++) s += red[t * 8 + p];
        bet[t] = s * 0.04419417382415922f;   // 1/sqrt(512)
    }
    __syncthreads();

    // ---- softmax over 64 (warp 0) ----
    if (t < 32) {
        float a0 = bet[t], a1 = bet[t + 32];
        float m = fmaxf(a0, a1);
        #pragma unroll
        for (int off = 16; off; off >>= 1)
            m = fmaxf(m, __shfl_xor_sync(0xffffffffu, m, off));
        float e0 = __expf(a0 - m), e1 = __expf(a1 - m);
        float s = e0 + e1;
        #pragma unroll
        for (int off = 16; off; off >>= 1)
            s += __shfl_xor_sync(0xffffffffu, s, off);
        float inv = 1.0f / s;
        bet[t] = e0 * inv;
        bet[t + 32] = e1 * inv;
    }
    __syncthreads();

    // ---- c[d] = sum_n beta[n] * y[n][d];  out = [x, c] overlaid into As ----
    float cval = 0.0f;
    #pragma unroll 8
    for (int n = 0; n < NN; n++)
        cval = fmaf(bet[n], __bfloat162float(Zs[n * Z_STRIDE + t]), cval);
    const float xval = __bfloat162float(Zs[64 * Z_STRIDE + t]);
    __syncthreads();                 // As no longer needed as A; reuse as out vector
    float* out_s = As;               // [1024]
    out_s[t]       = xval;
    out_s[512 + t] = cval;
    __syncthreads();

    // ---- o2 = out @ W2 + b2  (1024 -> 128) ----
    {
        const int j = t & 127;       // output col
        const int p = t >> 7;        // 0..3, 256 i's each
        const float* w2p = W2 + (size_t)(p * 256) * DD2 + j;
        const float* ov  = out_s + p * 256;
        float s = 0.0f;
        #pragma unroll 8
        for (int i = 0; i < 256; i++)
            s = fmaf(ov[i], w2p[(size_t)i * DD2], s);
        red[t] = s;                  // red[p*128 + j]
    }
    __syncthreads();
    if (t < 128) {
        o2[t] = red[t] + red[128 + t] + red[256 + t] + red[384 + t] + b2[t];
    }
    __syncthreads();

    // ---- softmax over 128 + mask + write ----
    if (t < 128) {
        float v = o2[t];
        float m = v;
        #pragma unroll
        for (int off = 16; off; off >>= 1)
            m = fmaxf(m, __shfl_xor_sync(0xffffffffu, m, off));
        if ((t & 31) == 0) msc[t >> 5] = m;
    }
    __syncthreads();
    if (t < 128) {
        const float m = fmaxf(fmaxf(msc[0], msc[1]), fmaxf(msc[2], msc[3]));
        const float e = __expf(o2[t] - m);
        red[t] = e;
        float s = e;
        #pragma unroll
        for (int off = 16; off; off >>= 1)
            s += __shfl_xor_sync(0xffffffffu, s, off);
        if ((t & 31) == 0) msc[4 + (t >> 5)] = s;
    }
    __syncthreads();
    if (t < 128) {
        const float s = msc[4] + msc[5] + msc[6] + msc[7];
        const float soft = red[t] / s;
        const float mv = (float)action_mask[(size_t)b * DD2 + t];
        out[(size_t)b * DD2 + t] = soft + NEGC * (1.0f - mv);
    }
}

extern "C" void kernel_launch(void* const* d_in, const int* in_sizes, int n_in,
                              void* d_out, int out_size)
{
    const float* obs_x       = (const float*)d_in[0];
    const float* others      = (const float*)d_in[1];
    const int*   action_mask = (const int*)  d_in[2];
    const float* W1          = (const float*)d_in[3];
    const float* b1          = (const float*)d_in[4];
    const float* W2          = (const float*)d_in[5];
    const float* b2          = (const float*)d_in[6];
    // d_in[7..10] = W3, b3, W4, b4: dead in reference forward(), unused.

    const size_t smem = (size_t)(65 * A_STRIDE + 32 * 512) * sizeof(float)
                      + (size_t)(65 * Z_STRIDE) * sizeof(__nv_bfloat16)
                      + (size_t)(512 + 64 + 128 + 8) * sizeof(float);

    cudaFuncSetAttribute(agent_policy_kernel,
                         cudaFuncAttributeMaxDynamicSharedMemorySize, (int)smem);
    agent_policy_kernel<<<BB, 512, smem>>>(obs_x, others, action_mask,
                                           W1, b1, W2, b2, (float*)d_out);
}

// round 2
// speedup vs baseline: 1.0012x; 1.0012x over previous
#include <cuda_runtime.h>
#include <cuda_bf16.h>

// AgentPolicy fused kernel.
// B=4096, N=64, FIN=256, D1=512, D2=128. One CTA per batch element.
// Pipeline per CTA:
//   A = [others[b] (64 rows); obs_x[b] (row 64)]  -> smem fp32
//   Z = A @ W1 + b1 (y rows 0..63, x row 64)       -> smem bf16, fp32 accum
//   alpha = x . y / sqrt(512); beta = softmax(alpha)
//   c = sum_n beta[n] * y[n]; out = [x, c] (1024)
//   o2 = softmax(out @ W2 + b2); logits = o2 + NEG*(1-mask)
// Value head (W3/b3/W4/b4) is dead in the reference -> skipped.

#define BB   4096
#define NN   64
#define FINN 256
#define DD1  512
#define DD2  128

#define A_STRIDE 264   // 256 + 8 pad (fp32)
#define Z_STRIDE 520   // 512 + 8 pad (bf16)
#define NEGC (-10000000.0f)

__global__ __launch_bounds__(512, 1)
void agent_policy_kernel(const float* __restrict__ obs_x,
                         const float* __restrict__ others,
                         const int*   __restrict__ action_mask,
                         const float* __restrict__ W1,
                         const float* __restrict__ b1,
                         const float* __restrict__ W2,
                         const float* __restrict__ b2,
                         float*       __restrict__ out)
{
    extern __shared__ char smem_raw[];
    float*          As  = (float*)smem_raw;                 // [65][264] fp32
    float*          Ws  = As + 65 * A_STRIDE;               // [32][512] fp32 (W1 k-tile)
    __nv_bfloat16*  Zs  = (__nv_bfloat16*)(Ws + 32 * 512);  // [65][520] bf16
    float*          red = (float*)(Zs + 65 * Z_STRIDE);     // [512]
    float*          bet = red + 512;                        // [64]
    float*          o2  = bet + 64;                         // [128]
    float*          msc = o2 + 128;                         // [8]

    const int t = threadIdx.x;
    const int b = blockIdx.x;

    // ---- load A: others[b] rows 0..63, obs_x[b] row 64 ----
    {
        const float* oth = others + (size_t)b * (NN * FINN);
        #pragma unroll
        for (int i = 0; i < 32; i++) {
            int idx = i * 512 + t;
            int n = idx >> 8;        // /256
            int f = idx & 255;
            As[n * A_STRIDE + f] = oth[idx];
        }
        if (t < FINN) As[64 * A_STRIDE + t] = obs_x[(size_t)b * FINN + t];
    }

    // ---- GEMM: Z[65][512] = A[65][256] @ W1[256][512] ----
    const int rg   = t >> 6;       // row group 0..7 (rows rg*8 .. rg*8+7)
    const int cg   = t & 63;       // col base; this thread owns cols cg + 64*j
    const int row0 = rg * 8;

    float acc[8][8];
    #pragma unroll
    for (int r = 0; r < 8; r++)
        #pragma unroll
        for (int j = 0; j < 8; j++)
            acc[r][j] = 0.0f;
    float xacc = 0.0f;

    for (int kt = 0; kt < 8; kt++) {
        __syncthreads();
        const float* w1p = W1 + (size_t)(kt * 32) * DD1;
        #pragma unroll
        for (int i = 0; i < 32; i++)
            Ws[i * 512 + t] = w1p[i * 512 + t];
        __syncthreads();

        const int kbase = kt * 32;
        #pragma unroll 4
        for (int k = 0; k < 32; k++) {
            const int kk = kbase + k;
            float aa[8], ww[8];
            #pragma unroll
            for (int r = 0; r < 8; r++) aa[r] = As[(row0 + r) * A_STRIDE + kk];
            #pragma unroll
            for (int j = 0; j < 8; j++) ww[j] = Ws[k * 512 + cg + 64 * j];
            #pragma unroll
            for (int r = 0; r < 8; r++)
                #pragma unroll
                for (int j = 0; j < 8; j++)
                    acc[r][j] = fmaf(aa[r], ww[j], acc[r][j]);
            // x row (row 64): thread t accumulates column t
            xacc = fmaf(As[64 * A_STRIDE + kk], Ws[k * 512 + t], xacc);
        }
    }

    // ---- epilogue: add b1, store Z as bf16 ----
    #pragma unroll
    for (int j = 0; j < 8; j++) {
        const int col = cg + 64 * j;
        const float bv = b1[col];
        #pragma unroll
        for (int r = 0; r < 8; r++)
            Zs[(row0 + r) * Z_STRIDE + col] = __float2bfloat16(acc[r][j] + bv);
    }
    Zs[64 * Z_STRIDE + t] = __float2bfloat16(xacc + b1[t]);
    __syncthreads();

    // ---- alpha[n] = x . y[n] / sqrt(512) ----
    {
        const int n = t >> 3;      // 0..63
        const int p = t & 7;       // 0..7, 64 d's each
        const __nv_bfloat16* yr = Zs + n * Z_STRIDE;
        const __nv_bfloat16* xr = Zs + 64 * Z_STRIDE;
        float s = 0.0f;
        #pragma unroll 8
        for (int d = 0; d < 64; d++) {
            int dd = p * 64 + d;
            s = fmaf(__bfloat162float(xr[dd]), __bfloat162float(yr[dd]), s);
        }
        red[t] = s;
    }
    __syncthreads();
    if (t < 64) {
        float s = 0.0f;
        #pragma unroll
        for (int p = 0; p < 8; p++) s += red[t * 8 + p];
        bet[t] = s * 0.04419417382415922f;   // 1/sqrt(512)
    }
    __syncthreads();

    // ---- softmax over 64 (warp 0) ----
    if (t < 32) {
        float a0 = bet[t], a1 = bet[t + 32];
        float m = fmaxf(a0, a1);
        #pragma unroll
        for (int off = 16; off; off >>= 1)
            m = fmaxf(m, __shfl_xor_sync(0xffffffffu, m, off));
        float e0 = __expf(a0 - m), e1 = __expf(a1 - m);
        float s = e0 + e1;
        #pragma unroll
        for (int off = 16; off; off >>= 1)
            s += __shfl_xor_sync(0xffffffffu, s, off);
        float inv = 1.0f / s;
        bet[t] = e0 * inv;
        bet[t + 32] = e1 * inv;
    }
    __syncthreads();

    // ---- c[d] = sum_n beta[n] * y[n][d];  out = [x, c] overlaid into As ----
    float cval = 0.0f;
    #pragma unroll 8
    for (int n = 0; n < NN; n++)
        cval = fmaf(bet[n], __bfloat162float(Zs[n * Z_STRIDE + t]), cval);
    const float xval = __bfloat162float(Zs[64 * Z_STRIDE + t]);
    __syncthreads();                 // As no longer needed as A; reuse as out vector
    float* out_s = As;               // [1024]
    out_s[t]       = xval;
    out_s[512 + t] = cval;
    __syncthreads();

    // ---- o2 = out @ W2 + b2  (1024 -> 128) ----
    {
        const int j = t & 127;       // output col
        const int p = t >> 7;        // 0..3, 256 i's each
        const float* w2p = W2 + (size_t)(p * 256) * DD2 + j;
        const float* ov  = out_s + p * 256;
        float s = 0.0f;
        #pragma unroll 8
        for (int i = 0; i < 256; i++)
            s = fmaf(ov[i], w2p[(size_t)i * DD2], s);
        red[t] = s;                  // red[p*128 + j]
    }
    __syncthreads();
    if (t < 128) {
        o2[t] = red[t] + red[128 + t] + red[256 + t] + red[384 + t] + b2[t];
    }
    __syncthreads();

    // ---- softmax over 128 + mask + write ----
    if (t < 128) {
        float v = o2[t];
        float m = v;
        #pragma unroll
        for (int off = 16; off; off >>= 1)
            m = fmaxf(m, __shfl_xor_sync(0xffffffffu, m, off));
        if ((t & 31) == 0) msc[t >> 5] = m;
    }
    __syncthreads();
    if (t < 128) {
        const float m = fmaxf(fmaxf(msc[0], msc[1]), fmaxf(msc[2], msc[3]));
        const float e = __expf(o2[t] - m);
        red[t] = e;
        float s = e;
        #pragma unroll
        for (int off = 16; off; off >>= 1)
            s += __shfl_xor_sync(0xffffffffu, s, off);
        if ((t & 31) == 0) msc[4 + (t >> 5)] = s;
    }
    __syncthreads();
    if (t < 128) {
        const float s = msc[4] + msc[5] + msc[6] + msc[7];
        const float soft = red[t] / s;
        const float mv = (float)action_mask[(size_t)b * DD2 + t];
        out[(size_t)b * DD2 + t] = soft + NEGC * (1.0f - mv);
    }
}

extern "C" void kernel_launch(void* const* d_in, const int* in_sizes, int n_in,
                              void* d_out, int out_size)
{
    const float* obs_x       = (const float*)d_in[0];
    const float* others      = (const float*)d_in[1];
    const int*   action_mask = (const int*)  d_in[2];
    const float* W1          = (const float*)d_in[3];
    const float* b1          = (const float*)d_in[4];
    const float* W2          = (const float*)d_in[5];
    const float* b2          = (const float*)d_in[6];
    // d_in[7..10] = W3, b3, W4, b4: dead in reference forward(), unused.

    const size_t smem = (size_t)(65 * A_STRIDE + 32 * 512) * sizeof(float)
                      + (size_t)(65 * Z_STRIDE) * sizeof(__nv_bfloat16)
                      + (size_t)(512 + 64 + 128 + 8) * sizeof(float);

    cudaFuncSetAttribute(agent_policy_kernel,
                         cudaFuncAttributeMaxDynamicSharedMemorySize, (int)smem);
    agent_policy_kernel<<<BB, 512, smem>>>(obs_x, others, action_mask,
                                           W1, b1, W2, b2, (float*)d_out);
}

// round 5
// speedup vs baseline: 3.8562x; 3.8517x over previous
#include <cuda_runtime.h>
#include <cuda_bf16.h>
#include <cstdint>

#define NEGC (-10000000.0f)

// ---------------- device globals (pre-converted weights) ----------------
__device__ __nv_bfloat16 g_W1T[512 * 256];   // W1T[n][k] = bf16(W1[k][n])
__device__ __nv_bfloat16 g_W2bf[1024 * 128]; // bf16 copy of W2

// ---------------- helpers ----------------
__device__ __forceinline__ uint32_t smem_u32(const void* p) {
    uint32_t a;
    asm("{ .reg .u64 t; cvta.to.shared.u64 t, %1; cvt.u32.u64 %0, t; }" : "=r"(a) : "l"(p));
    return a;
}
__device__ __forceinline__ uint32_t bf2_u32(__nv_bfloat162 h) { return *(uint32_t*)&h; }

__device__ __forceinline__ void ldsm4(uint32_t* r, uint32_t addr) {
    asm volatile("ldmatrix.sync.aligned.m8n8.x4.shared.b16 {%0,%1,%2,%3}, [%4];"
        : "=r"(r[0]), "=r"(r[1]), "=r"(r[2]), "=r"(r[3]) : "r"(addr));
}
__device__ __forceinline__ void mma16816(float* d, const uint32_t* a, const uint32_t* b) {
    asm volatile("mma.sync.aligned.m16n8k16.row.col.f32.bf16.bf16.f32 "
        "{%0,%1,%2,%3}, {%4,%5,%6,%7}, {%8,%9}, {%0,%1,%2,%3};"
        : "+f"(d[0]), "+f"(d[1]), "+f"(d[2]), "+f"(d[3])
        : "r"(a[0]), "r"(a[1]), "r"(a[2]), "r"(a[3]), "r"(b[0]), "r"(b[1]));
}

// ---------------- smem layout (bytes) ----------------
#define OFF_A    0u        // 65536: A tile [128 m x 256 k] bf16, swizzled
#define OFF_A2   65536u    // 8192 : A2 [16 x 256] bf16 (rows 0,1 = obs_x, rest 0)
#define OFF_B    73728u    // 16384: W1T chunk [128 n x 64 k] bf16, swizzled
#define OFF_Z    90112u    // 131072: Z [128 x 512] bf16, pair-XOR swizzle
#define OFF_XSF  221184u   // 4096 : x = obs@W1+b1, fp32 [2][512]
#define OFF_BS1  225280u   // 2048 : b1
#define OFF_BS2  227328u   // 512  : b2
#define SMEM_TOTAL 227840u
// scratch overlay on OFF_A after GEMM:
#define SC_RED   0u        // 2048 : f32[512]
#define SC_BET   2048u     // 512  : f32[128]
#define SC_C     2560u     // 4096 : f32[2][512] context c
#define SC_PART  6656u     // 8192 : float2[2][8][64]
#define SC_MSC   14848u    // 64

// Z pair access: row r, pair p (cols 2p,2p+1) -> byte offset
__device__ __forceinline__ uint32_t z_off(int r, int p) {
    return OFF_Z + (uint32_t)r * 1024u + ((uint32_t)(p ^ (r & 31)) << 2);
}

// ---------------- prep: convert weights to bf16 ----------------
__global__ void prep_kernel(const float* __restrict__ W1, const float* __restrict__ W2) {
    int i = blockIdx.x * blockDim.x + threadIdx.x;
    int stride = gridDim.x * blockDim.x;
    for (int idx = i; idx < 512 * 256; idx += stride) {
        int n = idx & 511, k = idx >> 9;
        g_W1T[n * 256 + k] = __float2bfloat16(W1[k * 512 + n]);
    }
    for (int idx = i; idx < 1024 * 128; idx += stride)
        g_W2bf[idx] = __float2bfloat16(W2[idx]);
}

// ---------------- main fused kernel: 2 batches per CTA ----------------
__global__ __launch_bounds__(512, 1)
void agent_main(const float* __restrict__ obs_x,
                const float* __restrict__ others,
                const int*   __restrict__ action_mask,
                const float* __restrict__ b1g,
                const float* __restrict__ b2g,
                float*       __restrict__ out)
{
    extern __shared__ char sm[];
    const uint32_t sb = smem_u32(sm);
    const int t = threadIdx.x, w = t >> 5, lane = t & 31;
    const int b0 = blockIdx.x * 2;

    float* bs1 = (float*)(sm + OFF_BS1);
    float* bs2 = (float*)(sm + OFF_BS2);
    float* xsf = (float*)(sm + OFF_XSF);

    bs1[t] = b1g[t];
    if (t < 128) bs2[t] = b2g[t];

    // ---- load A: others (2 batches) fp32 -> bf16, XOR-swizzled 16B units ----
    #pragma unroll
    for (int it = 0; it < 8; it++) {
        int idx = it * 512 + t;
        int row = idx >> 5, u = idx & 31;
        int up = (u & 24) | ((u ^ row) & 7);
        const float* src = others + (size_t)(b0 + (row >> 6)) * 16384 + (row & 63) * 256 + u * 8;
        float4 v0 = *(const float4*)src;
        float4 v1 = *(const float4*)(src + 4);
        uint4 pk = make_uint4(bf2_u32(__floats2bfloat162_rn(v0.x, v0.y)),
                              bf2_u32(__floats2bfloat162_rn(v0.z, v0.w)),
                              bf2_u32(__floats2bfloat162_rn(v1.x, v1.y)),
                              bf2_u32(__floats2bfloat162_rn(v1.z, v1.w)));
        *(uint4*)(sm + OFF_A + row * 512 + up * 16) = pk;
    }
    // ---- A2: rows 0,1 = obs_x rows (bf16); rows 2..15 zero ----
    {
        int row = t >> 5, u = t & 31;
        int up = (u & 24) | ((u ^ row) & 7);
        uint4 pk = make_uint4(0u, 0u, 0u, 0u);
        if (row < 2) {
            const float* src = obs_x + (size_t)(b0 + row) * 256 + u * 8;
            float4 v0 = *(const float4*)src;
            float4 v1 = *(const float4*)(src + 4);
            pk = make_uint4(bf2_u32(__floats2bfloat162_rn(v0.x, v0.y)),
                            bf2_u32(__floats2bfloat162_rn(v0.z, v0.w)),
                            bf2_u32(__floats2bfloat162_rn(v1.x, v1.y)),
                            bf2_u32(__floats2bfloat162_rn(v1.z, v1.w)));
        }
        *(uint4*)(sm + OFF_A2 + row * 512 + up * 16) = pk;
    }

    // ---- warp tiling: 8 m-slabs x 2 n-halves ----
    const int wm = w & 7, wn = w >> 3;
    const int m0 = wm * 16;
    const int lrow = lane & 15, lkh = lane >> 4;
    const int arow = m0 + lrow;
    const uint32_t a_base  = sb + OFF_A  + (uint32_t)arow * 512u;
    const uint32_t a2_base = sb + OFF_A2 + (uint32_t)lrow * 512u;
    const int g = lane >> 2, c = lane & 3;

    for (int pass = 0; pass < 4; pass++) {
        float acc[8][4];
        float oacc[4];
        #pragma unroll
        for (int nt = 0; nt < 8; nt++)
            #pragma unroll
            for (int i = 0; i < 4; i++) acc[nt][i] = 0.f;
        #pragma unroll
        for (int i = 0; i < 4; i++) oacc[i] = 0.f;

        for (int kc = 0; kc < 4; kc++) {
            __syncthreads();
            // load B chunk: W1T rows [pass*128, +128), k [kc*64, +64)
            #pragma unroll
            for (int it = 0; it < 2; it++) {
                int idx = it * 512 + t;
                int n = idx >> 3, u = idx & 7;
                int up = u ^ (n & 7);
                *(uint4*)(sm + OFF_B + n * 128 + up * 16) =
                    *(const uint4*)(g_W1T + (size_t)(pass * 128 + n) * 256 + kc * 64 + u * 8);
            }
            __syncthreads();

            #pragma unroll
            for (int ks = 0; ks < 4; ks++) {
                uint32_t af[4], a2f[4];
                int u = kc * 8 + ks * 2 + lkh;
                int up  = (u & 24) | ((u ^ arow) & 7);
                int up2 = (u & 24) | ((u ^ lrow) & 7);
                ldsm4(af,  a_base  + up  * 16);
                ldsm4(a2f, a2_base + up2 * 16);
                #pragma unroll
                for (int nt2 = 0; nt2 < 4; nt2++) {
                    uint32_t bf[4];
                    int n = wn * 64 + nt2 * 16 + lrow;
                    int ub = (ks * 2 + lkh) ^ (n & 7);
                    ldsm4(bf, sb + OFF_B + (uint32_t)n * 128u + (uint32_t)ub * 16u);
                    mma16816(acc[nt2 * 2],     af, bf);
                    mma16816(acc[nt2 * 2 + 1], af, bf + 2);
                    if (nt2 == ((w & 7) >> 1))
                        mma16816(oacc, a2f, bf + ((w & 1) << 1));
                }
            }
        }

        // ---- per-pass store: y tiles (+b1) -> Z bf16; obs rows -> xsf ----
        #pragma unroll
        for (int nt = 0; nt < 8; nt++) {
            int ncol = pass * 128 + wn * 64 + nt * 8 + 2 * c;
            float bv0 = bs1[ncol], bv1 = bs1[ncol + 1];
            int p = ncol >> 1;
            int r0 = m0 + g, r1 = m0 + g + 8;
            *(uint32_t*)(sm + z_off(r0, p)) =
                bf2_u32(__floats2bfloat162_rn(acc[nt][0] + bv0, acc[nt][1] + bv1));
            *(uint32_t*)(sm + z_off(r1, p)) =
                bf2_u32(__floats2bfloat162_rn(acc[nt][2] + bv0, acc[nt][3] + bv1));
        }
        if (lane < 8) {  // g in {0,1}: batch row of obs tile
            int col = pass * 128 + w * 8 + 2 * c;
            xsf[g * 512 + col]     = oacc[0] + bs1[col];
            xsf[g * 512 + col + 1] = oacc[1] + bs1[col + 1];
        }
    }
    __syncthreads();   // GEMM done; A region becomes scratch

    float* redp = (float*)(sm + SC_RED);
    float* betp = (float*)(sm + SC_BET);
    float* carr = (float*)(sm + SC_C);
    float* mscp = (float*)(sm + SC_MSC);

    // ---- alpha[n] = x . y[n] / sqrt(512) ----
    {
        int batch = t >> 8, tt = t & 255;
        int n = tt & 63, q = tt >> 6;
        int row = batch * 64 + n;
        const float* xv = xsf + batch * 512;
        float s = 0.f;
        #pragma unroll 8
        for (int pp = 0; pp < 64; pp++) {
            int p = q * 64 + pp;
            __nv_bfloat162 y2 = *(__nv_bfloat162*)(sm + z_off(row, p));
            float2 x2 = *(const float2*)(xv + 2 * p);
            s = fmaf(x2.x, __bfloat162float(y2.x), s);
            s = fmaf(x2.y, __bfloat162float(y2.y), s);
        }
        redp[t] = s;
    }
    __syncthreads();
    if (t < 128) {
        int batch = t >> 6, n = t & 63;
        const float* r = redp + batch * 256;
        betp[t] = (r[n] + r[64 + n] + r[128 + n] + r[192 + n]) * 0.04419417382415922f;
    }
    __syncthreads();
    if (w < 2) {  // softmax over 64: warp 0 -> batch0, warp 1 -> batch1
        float a0 = betp[w * 64 + lane], a1 = betp[w * 64 + 32 + lane];
        float m = fmaxf(a0, a1);
        #pragma unroll
        for (int off = 16; off; off >>= 1) m = fmaxf(m, __shfl_xor_sync(~0u, m, off));
        float e0 = __expf(a0 - m), e1 = __expf(a1 - m);
        float s = e0 + e1;
        #pragma unroll
        for (int off = 16; off; off >>= 1) s += __shfl_xor_sync(~0u, s, off);
        float inv = 1.0f / s;
        betp[w * 64 + lane] = e0 * inv;
        betp[w * 64 + 32 + lane] = e1 * inv;
    }
    __syncthreads();

    // ---- c[d] = sum_n beta[n] * y[n][d] ----
    {
        int batch = t >> 8, p = t & 255;
        float c0 = 0.f, c1 = 0.f;
        #pragma unroll 8
        for (int n = 0; n < 64; n++) {
            float be = betp[batch * 64 + n];
            __nv_bfloat162 y2 = *(__nv_bfloat162*)(sm + z_off(batch * 64 + n, p));
            c0 = fmaf(be, __bfloat162float(y2.x), c0);
            c1 = fmaf(be, __bfloat162float(y2.y), c1);
        }
        carr[batch * 512 + 2 * p]     = c0;
        carr[batch * 512 + 2 * p + 1] = c1;
    }
    __syncthreads();

    // ---- o2 = [x, c] @ W2 + b2: each W2 element read once, both batches ----
    {
        int q = t >> 6;      // k-chunk 0..7 (128 k each); k<512 -> x, else c
        int jp = t & 63;     // output col pair
        const __nv_bfloat16* w2p = g_W2bf + (size_t)(q * 128) * 128 + jp * 2;
        const float* base = (q < 4) ? (xsf + q * 128) : (carr + (q - 4) * 128);
        const float* ov0 = base;
        const float* ov1 = base + 512;
        float a00 = 0.f, a01 = 0.f, a10 = 0.f, a11 = 0.f;
        #pragma unroll 8
        for (int k = 0; k < 128; k++) {
            __nv_bfloat162 h = *(const __nv_bfloat162*)(w2p + (size_t)k * 128);
            float hx = __bfloat162float(h.x), hy = __bfloat162float(h.y);
            float v0 = ov0[k], v1 = ov1[k];
            a00 = fmaf(v0, hx, a00); a01 = fmaf(v0, hy, a01);
            a10 = fmaf(v1, hx, a10); a11 = fmaf(v1, hy, a11);
        }
        float2* p2 = (float2*)(sm + SC_PART);
        p2[q * 64 + jp]       = make_float2(a00, a01);
        p2[512 + q * 64 + jp] = make_float2(a10, a11);
    }
    __syncthreads();

    // ---- combine + softmax over 128 + mask + write ----
    float sval = 0.f, eval = 0.f;
    int batch = 0, j = 0;
    if (t < 256) {
        batch = t >> 7; j = t & 127;
        const float2* p2 = (const float2*)(sm + SC_PART) + batch * 512 + (j >> 1);
        float s = 0.f;
        #pragma unroll
        for (int q = 0; q < 8; q++) {
            float2 v = p2[q * 64];
            s += (j & 1) ? v.y : v.x;
        }
        sval = s + bs2[j];
        float m = sval;
        #pragma unroll
        for (int off = 16; off; off >>= 1) m = fmaxf(m, __shfl_xor_sync(~0u, m, off));
        if (lane == 0) mscp[w] = m;
    }
    __syncthreads();
    if (t < 256) {
        float m = fmaxf(fmaxf(mscp[batch * 4 + 0], mscp[batch * 4 + 1]),
                        fmaxf(mscp[batch * 4 + 2], mscp[batch * 4 + 3]));
        eval = __expf(sval - m);
        float ss = eval;
        #pragma unroll
        for (int off = 16; off; off >>= 1) ss += __shfl_xor_sync(~0u, ss, off);
        if (lane == 0) mscp[8 + w] = ss;
    }
    __syncthreads();
    if (t < 256) {
        float ssum = mscp[8 + batch * 4] + mscp[8 + batch * 4 + 1]
                   + mscp[8 + batch * 4 + 2] + mscp[8 + batch * 4 + 3];
        float soft = eval / ssum;
        float mv = (float)action_mask[(size_t)(b0 + batch) * 128 + j];
        out[(size_t)(b0 + batch) * 128 + j] = soft + NEGC * (1.0f - mv);
    }
}

extern "C" void kernel_launch(void* const* d_in, const int* in_sizes, int n_in,
                              void* d_out, int out_size)
{
    const float* obs_x       = (const float*)d_in[0];
    const float* others      = (const float*)d_in[1];
    const int*   action_mask = (const int*)  d_in[2];
    const float* W1          = (const float*)d_in[3];
    const float* b1          = (const float*)d_in[4];
    const float* W2          = (const float*)d_in[5];
    const float* b2          = (const float*)d_in[6];
    // d_in[7..10] = W3,b3,W4,b4: dead in reference forward(), unused.

    prep_kernel<<<256, 256>>>(W1, W2);

    cudaFuncSetAttribute(agent_main,
                         cudaFuncAttributeMaxDynamicSharedMemorySize, (int)SMEM_TOTAL);
    agent_main<<<2048, 512, SMEM_TOTAL>>>(obs_x, others, action_mask,
                                          b1, b2, (float*)d_out);
}

// round 6
// speedup vs baseline: 4.6820x; 1.2142x over previous
#include <cuda_runtime.h>
#include <cuda_fp16.h>
#include <cstdint>

#define NEGC (-10000000.0f)

// ---------------- device globals (pre-converted weights, fp16) ----------------
__device__ __half g_W1h[512 * 256];   // W1T[n][k] = h(W1[k][n])
__device__ __half g_W2h[1024 * 128];  // fp16 copy of W2

// ---------------- helpers ----------------
__device__ __forceinline__ uint32_t smem_u32(const void* p) {
    uint32_t a;
    asm("{ .reg .u64 t; cvta.to.shared.u64 t, %1; cvt.u32.u64 %0, t; }" : "=r"(a) : "l"(p));
    return a;
}
__device__ __forceinline__ uint32_t h2_u32(__half2 h) { return *(uint32_t*)&h; }

__device__ __forceinline__ void ldsm4(uint32_t* r, uint32_t addr) {
    asm volatile("ldmatrix.sync.aligned.m8n8.x4.shared.b16 {%0,%1,%2,%3}, [%4];"
        : "=r"(r[0]), "=r"(r[1]), "=r"(r[2]), "=r"(r[3]) : "r"(addr));
}
// f16-accumulate MMA
__device__ __forceinline__ void mmah(uint32_t* d, const uint32_t* a, const uint32_t* b) {
    asm volatile("mma.sync.aligned.m16n8k16.row.col.f16.f16.f16.f16 "
        "{%0,%1}, {%2,%3,%4,%5}, {%6,%7}, {%0,%1};"
        : "+r"(d[0]), "+r"(d[1])
        : "r"(a[0]), "r"(a[1]), "r"(a[2]), "r"(a[3]), "r"(b[0]), "r"(b[1]));
}

// ---------------- smem layout (bytes) ----------------
#define OFF_A     0u        // 65536 : A [128 m x 256 k] f16, swizzled
#define OFF_A2    65536u    // 8192  : A2 [16 x 256] f16 (rows 0,1 = obs_x)
#define OFF_B     73728u    // 32768 : B double buffer (2 x [128 n x 64 k] f16); Z block3 overlays
#define OFF_Z012  106496u   // 98304 : Z blocks 0..2 ([128 r x 128 c] f16 each)
#define OFF_XSF   204800u   // 2048  : x f16 [2][512]
#define OFF_BS1   206848u   // 1024  : b1 f16
#define OFF_BS2   207872u   // 256   : b2 f16
#define SMEM_TOTAL 208128u
// scratch overlay on OFF_A after GEMM:
#define SC_RED   0u
#define SC_BET   2048u
#define SC_C     2560u
#define SC_PART  6656u
#define SC_MSC   14848u

// Z address: row r, global col-pair p (cols 2p,2p+1). Pass-major blocks of 64 pairs.
__device__ __forceinline__ uint32_t zaddr(int r, int p) {
    int blk = p >> 6, pl = p & 63;
    uint32_t base = (blk < 3) ? (OFF_Z012 + (uint32_t)blk * 32768u) : OFF_B;
    return base + (uint32_t)r * 256u + ((uint32_t)(pl ^ (r & 63)) << 2);
}

// ---------------- prep: convert weights to fp16 ----------------
__global__ void prep_kernel(const float* __restrict__ W1, const float* __restrict__ W2) {
    int i = blockIdx.x * blockDim.x + threadIdx.x;
    int stride = gridDim.x * blockDim.x;
    for (int idx = i; idx < 512 * 256; idx += stride) {
        int n = idx & 511, k = idx >> 9;
        g_W1h[n * 256 + k] = __float2half(W1[k * 512 + n]);
    }
    for (int idx = i; idx < 1024 * 128; idx += stride)
        g_W2h[idx] = __float2half(W2[idx]);
}

// issue cp.async for W1 chunk ci into buffer ci&1
__device__ __forceinline__ void load_chunk(uint32_t sb, int ci, int t) {
    uint32_t dst = sb + OFF_B + ((ci & 1) ? 16384u : 0u);
    const __half* src = g_W1h + (size_t)((ci >> 2) * 128) * 256 + (ci & 3) * 64;
    #pragma unroll
    for (int i = 0; i < 2; i++) {
        int idx = i * 512 + t;
        int n = idx >> 3, u = idx & 7;
        int up = u ^ (n & 7);
        uint32_t d = dst + (uint32_t)n * 128u + (uint32_t)up * 16u;
        const void* s = src + (size_t)n * 256 + u * 8;
        asm volatile("cp.async.cg.shared.global [%0], [%1], 16;" :: "r"(d), "l"(s));
    }
    asm volatile("cp.async.commit_group;" ::: "memory");
}

// ---------------- main fused kernel: 2 batches per CTA ----------------
__global__ __launch_bounds__(512, 1)
void agent_main(const float* __restrict__ obs_x,
                const float* __restrict__ others,
                const int*   __restrict__ action_mask,
                const float* __restrict__ b1g,
                const float* __restrict__ b2g,
                float*       __restrict__ out)
{
    extern __shared__ char sm[];
    const uint32_t sb = smem_u32(sm);
    const int t = threadIdx.x, w = t >> 5, lane = t & 31;
    const int b0 = blockIdx.x * 2;

    __half* bs1h = (__half*)(sm + OFF_BS1);
    __half* bs2h = (__half*)(sm + OFF_BS2);
    __half* xsfh = (__half*)(sm + OFF_XSF);

    bs1h[t] = __float2half(b1g[t]);
    if (t < 128) bs2h[t] = __float2half(b2g[t]);

    // kick off W1 chunk 0 ASAP
    load_chunk(sb, 0, t);

    // ---- A: others (2 batches) fp32 -> f16, XOR-swizzled 16B units ----
    #pragma unroll
    for (int it = 0; it < 8; it++) {
        int idx = it * 512 + t;
        int row = idx >> 5, u = idx & 31;
        int up = (u & 24) | ((u ^ row) & 7);
        const float* src = others + (size_t)(b0 + (row >> 6)) * 16384 + (row & 63) * 256 + u * 8;
        float4 v0 = *(const float4*)src;
        float4 v1 = *(const float4*)(src + 4);
        uint4 pk = make_uint4(h2_u32(__floats2half2_rn(v0.x, v0.y)),
                              h2_u32(__floats2half2_rn(v0.z, v0.w)),
                              h2_u32(__floats2half2_rn(v1.x, v1.y)),
                              h2_u32(__floats2half2_rn(v1.z, v1.w)));
        *(uint4*)(sm + OFF_A + row * 512 + up * 16) = pk;
    }
    // ---- A2: rows 0,1 = obs_x, rows 2..15 = 0 ----
    {
        int row = t >> 5, u = t & 31;
        int up = (u & 24) | ((u ^ row) & 7);
        uint4 pk = make_uint4(0u, 0u, 0u, 0u);
        if (row < 2) {
            const float* src = obs_x + (size_t)(b0 + row) * 256 + u * 8;
            float4 v0 = *(const float4*)src;
            float4 v1 = *(const float4*)(src + 4);
            pk = make_uint4(h2_u32(__floats2half2_rn(v0.x, v0.y)),
                            h2_u32(__floats2half2_rn(v0.z, v0.w)),
                            h2_u32(__floats2half2_rn(v1.x, v1.y)),
                            h2_u32(__floats2half2_rn(v1.z, v1.w)));
        }
        *(uint4*)(sm + OFF_A2 + row * 512 + up * 16) = pk;
    }

    // ---- warp tiling: 4 m-slabs (32 rows) x 4 n-quarters (32 cols of the 128-col pass) ----
    const int wm = w & 3, wn = w >> 2;
    const int m0 = wm * 32;
    const int lrow = lane & 15, lkh = lane >> 4;
    const int arow0 = m0 + lrow, arow1 = m0 + 16 + lrow;
    const uint32_t a_base0 = sb + OFF_A + (uint32_t)arow0 * 512u;
    const uint32_t a_base1 = sb + OFF_A + (uint32_t)arow1 * 512u;
    const uint32_t a2_base = sb + OFF_A2 + (uint32_t)lrow * 512u;
    const int g = lane >> 2, c = lane & 3;

    uint32_t acc[2][4][2];
    uint32_t oacc[2];

    for (int ci = 0; ci < 16; ci++) {
        const int pass = ci >> 2, kc = ci & 3;
        asm volatile("cp.async.wait_group 0;" ::: "memory");
        __syncthreads();
        if (ci < 15) load_chunk(sb, ci + 1, t);

        if (kc == 0) {
            #pragma unroll
            for (int mi = 0; mi < 2; mi++)
                #pragma unroll
                for (int ni = 0; ni < 4; ni++) { acc[mi][ni][0] = 0u; acc[mi][ni][1] = 0u; }
            oacc[0] = 0u; oacc[1] = 0u;
        }

        const uint32_t bbuf = sb + OFF_B + ((ci & 1) ? 16384u : 0u);
        #pragma unroll
        for (int ks = 0; ks < 4; ks++) {
            const int u = kc * 8 + ks * 2 + lkh;
            uint32_t af0[4], af1[4], a2f[4];
            ldsm4(af0, a_base0 + (uint32_t)(((u & 24) | ((u ^ arow0) & 7)) << 4));
            ldsm4(af1, a_base1 + (uint32_t)(((u & 24) | ((u ^ arow1) & 7)) << 4));
            ldsm4(a2f, a2_base + (uint32_t)(((u & 24) | ((u ^ lrow) & 7)) << 4));
            uint32_t bf0[4], bf1[4];
            const int n0 = wn * 32 + lrow, n1 = n0 + 16;
            ldsm4(bf0, bbuf + (uint32_t)n0 * 128u + (uint32_t)(((ks * 2 + lkh) ^ (n0 & 7)) << 4));
            ldsm4(bf1, bbuf + (uint32_t)n1 * 128u + (uint32_t)(((ks * 2 + lkh) ^ (n1 & 7)) << 4));

            mmah(acc[0][0], af0, bf0);      mmah(acc[0][1], af0, bf0 + 2);
            mmah(acc[0][2], af0, bf1);      mmah(acc[0][3], af0, bf1 + 2);
            mmah(acc[1][0], af1, bf0);      mmah(acc[1][1], af1, bf0 + 2);
            mmah(acc[1][2], af1, bf1);      mmah(acc[1][3], af1, bf1 + 2);
            const uint32_t* bt = (wm == 0) ? bf0 : (wm == 1) ? (bf0 + 2)
                               : (wm == 2) ? bf1 : (bf1 + 2);
            mmah(oacc, a2f, bt);
        }

        if (kc == 3) {
            if (pass == 3) __syncthreads();  // B buffers die; Z block3 overlays them
            #pragma unroll
            for (int mi = 0; mi < 2; mi++)
                #pragma unroll
                for (int ni = 0; ni < 4; ni++) {
                    const int ncol = pass * 128 + wn * 32 + ni * 8 + 2 * c;
                    const __half2 bias = *(__half2*)(sm + OFF_BS1 + ncol * 2);
                    const int p = ncol >> 1;
                    const int r0 = m0 + mi * 16 + g;
                    *(__half2*)(sm + zaddr(r0, p)) =
                        __hadd2(*(__half2*)&acc[mi][ni][0], bias);
                    *(__half2*)(sm + zaddr(r0 + 8, p)) =
                        __hadd2(*(__half2*)&acc[mi][ni][1], bias);
                }
            if (g < 2) {  // obs rows -> xsf (g = batch)
                const int col = pass * 128 + wn * 32 + wm * 8 + 2 * c;
                const __half2 bias = *(__half2*)(sm + OFF_BS1 + col * 2);
                *(__half2*)(sm + OFF_XSF + (g * 512 + col) * 2) =
                    __hadd2(*(__half2*)&oacc[0], bias);
            }
        }
    }
    __syncthreads();   // GEMM done; A region becomes scratch

    float* redp = (float*)(sm + SC_RED);
    float* betp = (float*)(sm + SC_BET);
    float* carr = (float*)(sm + SC_C);
    float* mscp = (float*)(sm + SC_MSC);

    // ---- alpha[n] = x . y[n] / sqrt(512) ----
    {
        int batch = t >> 8, tt = t & 255;
        int n = tt & 63, q = tt >> 6;
        int row = batch * 64 + n;
        const __half* xh = xsfh + batch * 512;
        float s = 0.f;
        #pragma unroll 8
        for (int pp = 0; pp < 64; pp++) {
            int p = q * 64 + pp;
            float2 yf = __half22float2(*(__half2*)(sm + zaddr(row, p)));
            float2 xf = __half22float2(*(const __half2*)(xh + 2 * p));
            s = fmaf(xf.x, yf.x, s);
            s = fmaf(xf.y, yf.y, s);
        }
        redp[t] = s;
    }
    __syncthreads();
    if (t < 128) {
        int batch = t >> 6, n = t & 63;
        const float* r = redp + batch * 256;
        betp[t] = (r[n] + r[64 + n] + r[128 + n] + r[192 + n]) * 0.04419417382415922f;
    }
    __syncthreads();
    if (w < 2) {  // softmax over 64
        float a0 = betp[w * 64 + lane], a1 = betp[w * 64 + 32 + lane];
        float m = fmaxf(a0, a1);
        #pragma unroll
        for (int off = 16; off; off >>= 1) m = fmaxf(m, __shfl_xor_sync(~0u, m, off));
        float e0 = __expf(a0 - m), e1 = __expf(a1 - m);
        float s = e0 + e1;
        #pragma unroll
        for (int off = 16; off; off >>= 1) s += __shfl_xor_sync(~0u, s, off);
        float inv = 1.0f / s;
        betp[w * 64 + lane] = e0 * inv;
        betp[w * 64 + 32 + lane] = e1 * inv;
    }
    __syncthreads();

    // ---- c[d] = sum_n beta[n] * y[n][d] ----
    {
        int batch = t >> 8, p = t & 255;
        float c0 = 0.f, c1 = 0.f;
        #pragma unroll 8
        for (int n = 0; n < 64; n++) {
            float be = betp[batch * 64 + n];
            float2 yf = __half22float2(*(__half2*)(sm + zaddr(batch * 64 + n, p)));
            c0 = fmaf(be, yf.x, c0);
            c1 = fmaf(be, yf.y, c1);
        }
        carr[batch * 512 + 2 * p]     = c0;
        carr[batch * 512 + 2 * p + 1] = c1;
    }
    __syncthreads();

    // ---- o2 = [x, c] @ W2 + b2: W2 read once, both batches ----
    {
        int q = t >> 6;      // k-chunk 0..7 of 128; q<4 -> x (f16), else c (f32)
        int jp = t & 63;
        const __half* w2p = g_W2h + (size_t)(q * 128) * 128 + jp * 2;
        float a00 = 0.f, a01 = 0.f, a10 = 0.f, a11 = 0.f;
        if (q < 4) {
            const __half* x0 = xsfh + q * 128;
            const __half* x1 = x0 + 512;
            #pragma unroll 8
            for (int k = 0; k < 128; k++) {
                float2 hf = __half22float2(*(const __half2*)(w2p + (size_t)k * 128));
                float v0 = __half2float(x0[k]), v1 = __half2float(x1[k]);
                a00 = fmaf(v0, hf.x, a00); a01 = fmaf(v0, hf.y, a01);
                a10 = fmaf(v1, hf.x, a10); a11 = fmaf(v1, hf.y, a11);
            }
        } else {
            const float* c0p = carr + (q - 4) * 128;
            const float* c1p = c0p + 512;
            #pragma unroll 8
            for (int k = 0; k < 128; k++) {
                float2 hf = __half22float2(*(const __half2*)(w2p + (size_t)k * 128));
                float v0 = c0p[k], v1 = c1p[k];
                a00 = fmaf(v0, hf.x, a00); a01 = fmaf(v0, hf.y, a01);
                a10 = fmaf(v1, hf.x, a10); a11 = fmaf(v1, hf.y, a11);
            }
        }
        float2* p2 = (float2*)(sm + SC_PART);
        p2[q * 64 + jp]       = make_float2(a00, a01);
        p2[512 + q * 64 + jp] = make_float2(a10, a11);
    }
    __syncthreads();

    // ---- combine + softmax over 128 + mask + write ----
    float sval = 0.f, eval = 0.f;
    int batch = 0, j = 0;
    if (t < 256) {
        batch = t >> 7; j = t & 127;
        const float2* p2 = (const float2*)(sm + SC_PART) + batch * 512 + (j >> 1);
        float s = 0.f;
        #pragma unroll
        for (int q = 0; q < 8; q++) {
            float2 v = p2[q * 64];
            s += (j & 1) ? v.y : v.x;
        }
        sval = s + __half2float(bs2h[j]);
        float m = sval;
        #pragma unroll
        for (int off = 16; off; off >>= 1) m = fmaxf(m, __shfl_xor_sync(~0u, m, off));
        if (lane == 0) mscp[w] = m;
    }
    __syncthreads();
    if (t < 256) {
        float m = fmaxf(fmaxf(mscp[batch * 4 + 0], mscp[batch * 4 + 1]),
                        fmaxf(mscp[batch * 4 + 2], mscp[batch * 4 + 3]));
        eval = __expf(sval - m);
        float ss = eval;
        #pragma unroll
        for (int off = 16; off; off >>= 1) ss += __shfl_xor_sync(~0u, ss, off);
        if (lane == 0) mscp[8 + w] = ss;
    }
    __syncthreads();
    if (t < 256) {
        float ssum = mscp[8 + batch * 4] + mscp[8 + batch * 4 + 1]
                   + mscp[8 + batch * 4 + 2] + mscp[8 + batch * 4 + 3];
        float soft = eval / ssum;
        float mv = (float)action_mask[(size_t)(b0 + batch) * 128 + j];
        out[(size_t)(b0 + batch) * 128 + j] = soft + NEGC * (1.0f - mv);
    }
}

extern "C" void kernel_launch(void* const* d_in, const int* in_sizes, int n_in,
                              void* d_out, int out_size)
{
    const float* obs_x       = (const float*)d_in[0];
    const float* others      = (const float*)d_in[1];
    const int*   action_mask = (const int*)  d_in[2];
    const float* W1          = (const float*)d_in[3];
    const float* b1          = (const float*)d_in[4];
    const float* W2          = (const float*)d_in[5];
    const float* b2          = (const float*)d_in[6];
    // d_in[7..10] = W3,b3,W4,b4: dead in reference forward(), unused.

    prep_kernel<<<256, 256>>>(W1, W2);

    cudaFuncSetAttribute(agent_main,
                         cudaFuncAttributeMaxDynamicSharedMemorySize, (int)SMEM_TOTAL);
    agent_main<<<2048, 512, SMEM_TOTAL>>>(obs_x, others, action_mask,
                                          b1, b2, (float*)d_out);
}